// round 1
// baseline (speedup 1.0000x reference)
#include <cuda_runtime.h>
#include <cstdint>
#include <cstddef>

// depthwise conv1d: B=8, L=16384, C=512, K=31, SAME padding, fp32.
// Strategy: channel-pair packing (f32x2 FMA), ring of 32 accumulators,
// 1 LDG.64 + 31 FFMA2 + 1 STG.64 per packed output. Exact 1x HBM traffic.

constexpr int B_   = 8;
constexpr int L_   = 16384;
constexpr int C_   = 512;
constexpr int K_   = 31;
constexpr int PAD_ = 15;

constexpr int RCH  = 256;      // L-positions per thread chunk
constexpr int TPB  = 128;      // threads per block (each = one channel pair)
constexpr int CW   = C_ / 2;   // row stride in u64 (float2) units = 256

using u64 = unsigned long long;

__device__ __forceinline__ u64 ffma2(u64 a, u64 b, u64 c) {
    u64 d;
    asm("fma.rn.f32x2 %0, %1, %2, %3;" : "=l"(d) : "l"(a), "l"(b), "l"(c));
    return d;
}

template <bool GUARD>
__device__ __forceinline__ void conv_body(const u64* __restrict__ xg,
                                          const u64* __restrict__ wg,
                                          const u64* __restrict__ bg,
                                          u64* __restrict__ og)
{
    const int cp = blockIdx.y * TPB + threadIdx.x;   // channel pair 0..255
    const int b  = blockIdx.z;
    const int l0 = blockIdx.x * RCH;

    const u64* xp = xg + (size_t)b * L_ * CW + cp;
    u64*       op = og + (size_t)b * L_ * CW + (size_t)l0 * CW + cp;

    // weights for this channel pair: kernel layout [K, C] (last dim 1 squeezed)
    u64 wr[K_];
#pragma unroll
    for (int k = 0; k < K_; ++k) wr[k] = wg[k * CW + cp];
    const u64 bb = bg[cp];

    // ring of 32 f32x2 accumulators, pre-seeded with bias
    u64 acc[32];
#pragma unroll
    for (int i = 0; i < 32; ++i) acc[i] = bb;

    // ---- prologue: inputs x[l0-15 .. l0+14] (steps s = 0..29, no stores) ----
    // input q = l0-15+s contributes w[k] to out[l0 + s - k]; clip k<=s so we
    // never touch slots belonging to the previous chunk.
    {
        const u64* pp = xp + (ptrdiff_t)(l0 - PAD_) * CW;
#pragma unroll
        for (int s = 0; s < 30; ++s) {
            u64 v = 0ULL;
            if (!GUARD || (l0 - PAD_ + s) >= 0) v = pp[(ptrdiff_t)s * CW];
#pragma unroll
            for (int k = 0; k <= s; ++k) {
                const int t = s - k;                  // slot, always 0..29 here
                acc[t] = ffma2(v, wr[k], acc[t]);
            }
        }
    }

    // ---- main loop: m = 0..RCH-1 ; input q = l0+15+m ----
    // step m: input contributes w[k] to slot (30 + m - k) & 31 (k = 0..30);
    // then out[l0+m] (slot m&31) is complete -> store, reset slot to bias.
    // Contributions to outputs beyond the chunk land in slots strictly after
    // that slot's final store, so they are harmlessly discarded.
    const u64* ip = xp + (size_t)(l0 + PAD_) * CW;
    u64*       sp = op;
    for (int m8 = 0; m8 < RCH / 32; ++m8) {
#pragma unroll
        for (int u = 0; u < 32; ++u) {
            u64 v = 0ULL;
            if (!GUARD || (l0 + PAD_ + m8 * 32 + u) < L_) v = ip[u * CW];
#pragma unroll
            for (int k = 0; k < K_; ++k) {
                const int t = (30 + u - k) & 31;
                acc[t] = ffma2(v, wr[k], acc[t]);
            }
            sp[u * CW] = acc[u];
            acc[u] = bb;
        }
        ip += 32 * CW;
        sp += 32 * CW;
    }
}

__global__ void __launch_bounds__(TPB, 3)
depthconv1d_kernel(const float* __restrict__ x,
                   const float* __restrict__ w,
                   const float* __restrict__ bias,
                   float* __restrict__ out)
{
    const u64* xg = reinterpret_cast<const u64*>(x);
    const u64* wg = reinterpret_cast<const u64*>(w);
    const u64* bg = reinterpret_cast<const u64*>(bias);
    u64*       og = reinterpret_cast<u64*>(out);

    // only the first and last L-chunks touch the padded boundary
    if (blockIdx.x == 0 || blockIdx.x == (L_ / RCH) - 1) {
        conv_body<true>(xg, wg, bg, og);
    } else {
        conv_body<false>(xg, wg, bg, og);
    }
}

extern "C" void kernel_launch(void* const* d_in, const int* in_sizes, int n_in,
                              void* d_out, int out_size)
{
    const float* x    = (const float*)d_in[0];   // [B, L, C]
    const float* w    = (const float*)d_in[1];   // [K, C, 1]
    const float* bias = (const float*)d_in[2];   // [C]
    float*       out  = (float*)d_out;           // [B, L, C]

    dim3 grid(L_ / RCH, (C_ / 2) / TPB, B_);     // (64, 2, 8)
    depthconv1d_kernel<<<grid, TPB>>>(x, w, bias, out);
}

// round 2
// speedup vs baseline: 1.2411x; 1.2411x over previous
#include <cuda_runtime.h>
#include <cstdint>
#include <cstddef>

// Depthwise conv1d: B=8, L=16384, C=512, K=31, SAME, fp32.
// cp.async -> SMEM slab pipeline + f32x2 ring-accumulator stencil.
// Ring of 32 f32x2 accumulators; input stream s=0..287, q = l0-16+s.
// Input q contributes w[k] to out[q+15-k]; out o stored at step s = o-l0+31.

constexpr int B_   = 8;
constexpr int L_   = 16384;
constexpr int C_   = 512;
constexpr int K_   = 31;
constexpr int RCH  = 256;          // L outputs per block
constexpr int TPB  = 128;          // 4 warps; warp owns 32 channel pairs
constexpr int CW   = C_ / 2;       // 256 u64 per L-row
constexpr int SLAB = 16;           // L-rows per smem slab
constexpr int ROWB = 2048;         // bytes per L-row (512 floats)

using u64 = unsigned long long;

__device__ __forceinline__ u64 ffma2(u64 a, u64 b, u64 c) {
    u64 d;
    asm("fma.rn.f32x2 %0, %1, %2, %3;" : "=l"(d) : "l"(a), "l"(b), "l"(c));
    return d;
}
__device__ __forceinline__ void cpa16(unsigned saddr, const void* gptr, unsigned sz) {
    asm volatile("cp.async.cg.shared.global [%0], [%1], 16, %2;\n"
                 :: "r"(saddr), "l"(gptr), "r"(sz));
}
__device__ __forceinline__ void cpcommit() { asm volatile("cp.async.commit_group;\n"); }
template <int N>
__device__ __forceinline__ void cpwait() { asm volatile("cp.async.wait_group %0;\n" :: "n"(N)); }

struct Copier {
    const char* xw;     // x base for this (batch, warp's first channel pair)
    unsigned    sbase;  // shared addr of this warp's buffer[0]
    int         lane;
    int         q0;     // l0 - 16

    // Copy slab (16 L-rows x 256B for this warp) into buffer buf.
    // OOB rows (SAME padding) zero-filled via src_size = 0.
    __device__ __forceinline__ void issue(int slab, int buf) const {
        unsigned dst = sbase + (unsigned)buf * (SLAB * 256);
        int qb = q0 + slab * SLAB;
#pragma unroll
        for (int j = 0; j < 8; ++j) {
            int idx = j * 32 + lane;        // 0..255 chunks of 16B
            int r = idx >> 4, o = idx & 15;
            int q = qb + r;
            int qc = q < 0 ? 0 : (q >= L_ ? L_ - 1 : q);
            unsigned sz = (q >= 0 && q < L_) ? 16u : 0u;
            cpa16(dst + (unsigned)(r * 256 + o * 16),
                  xw + (long)qc * ROWB + o * 16, sz);
        }
        cpcommit();
    }
};

__global__ void __launch_bounds__(TPB, 3)
dwconv_kernel(const float* __restrict__ x, const float* __restrict__ w,
              const float* __restrict__ bias, float* __restrict__ out)
{
    __shared__ __align__(16) u64 sbuf[4][3][SLAB][32];   // 48 KB

    const int lane = threadIdx.x & 31;
    const int warp = threadIdx.x >> 5;
    const int cp   = blockIdx.y * TPB + threadIdx.x;     // channel pair 0..255
    const int cp0w = blockIdx.y * TPB + warp * 32;       // warp's first pair
    const int b    = blockIdx.z;
    const int l0   = blockIdx.x * RCH;

    Copier cc;
    cc.xw    = (const char*)x + (size_t)b * ((size_t)L_ * C_ * 4) + (size_t)cp0w * 8;
    cc.sbase = (unsigned)__cvta_generic_to_shared(&sbuf[warp][0][0][0]);
    cc.lane  = lane;
    cc.q0    = l0 - 16;

    // per-channel-pair weights + bias
    const u64* wg = (const u64*)w;
    u64 wr[K_];
#pragma unroll
    for (int k = 0; k < K_; ++k) wr[k] = wg[k * CW + cp];
    const u64 bb = ((const u64*)bias)[cp];

    u64 acc[32];
#pragma unroll
    for (int i = 0; i < 32; ++i) acc[i] = bb;

    u64* op = (u64*)out + (size_t)b * ((size_t)L_ * CW) + (size_t)l0 * CW + cp;

    cc.issue(0, 0); cc.issue(1, 1); cc.issue(2, 2);
    const u64* sw = &sbuf[warp][0][0][0];

    // ---- prologue slab 0: s = u (0..15); contributions k <= s-1 ----
    cpwait<2>(); __syncthreads();
#pragma unroll
    for (int u = 1; u < 16; ++u) {
        u64 v = sw[u * 32 + lane];
#pragma unroll
        for (int k = 0; k < u; ++k) {                // slot = s-1-k, no wrap
            int t = u - 1 - k;
            acc[t] = ffma2(v, wr[k], acc[t]);
        }
    }
    __syncthreads(); cc.issue(3, 0);

    // ---- prologue slab 1: s = 16+u; k <= 15+u; store out[l0] at s=31 ----
    cpwait<2>(); __syncthreads();
#pragma unroll
    for (int u = 0; u < 16; ++u) {
        u64 v = sw[(SLAB * 32) + u * 32 + lane];
#pragma unroll
        for (int k = 0; k <= 15 + u; ++k) {          // 15+u <= 30
            int t = 15 + u - k;
            acc[t] = ffma2(v, wr[k], acc[t]);
        }
        if (u == 15) { *op = acc[0]; acc[0] = bb; op += CW; }
    }
    __syncthreads(); cc.issue(4, 1);

    // ---- main: s = 32 + 32*t8 + 16*h + u ; slab = 2 + 2*t8 + h ----
    for (int t8 = 0; t8 < 8; ++t8) {
        const int bh0 = 2 - (t8 % 3);                // (2+2*t8) % 3
        // h = 0
        {
            if (t8 == 7) cpwait<1>(); else cpwait<2>();
            __syncthreads();
            const u64* sl = sw + bh0 * (SLAB * 32);
#pragma unroll
            for (int u = 0; u < 16; ++u) {
                u64 v = sl[u * 32 + lane];
#pragma unroll
                for (int k = 0; k < K_; ++k) {
                    int tt = (u - 1 - k) & 31;
                    acc[tt] = ffma2(v, wr[k], acc[tt]);
                }
                int st = (u + 1) & 31;               // out[l0 + s - 31]
                *op = acc[st]; acc[st] = bb; op += CW;
            }
            __syncthreads();
            int ns = 2 + 2 * t8 + 3;
            if (ns <= 17) cc.issue(ns, bh0);
        }
        // h = 1
        {
            const int bh1 = (bh0 == 2) ? 0 : bh0 + 1;
            if (t8 == 7) cpwait<0>(); else cpwait<2>();
            __syncthreads();
            const u64* sl = sw + bh1 * (SLAB * 32);
#pragma unroll
            for (int u = 0; u < 16; ++u) {
                u64 v = sl[u * 32 + lane];
#pragma unroll
                for (int k = 0; k < K_; ++k) {
                    int tt = (16 + u - 1 - k) & 31;
                    acc[tt] = ffma2(v, wr[k], acc[tt]);
                }
                int st = (16 + u + 1) & 31;
                if (u < 15 || t8 < 7) {              // skip s=287 (no output)
                    *op = acc[st]; acc[st] = bb; op += CW;
                }
            }
            __syncthreads();
            int ns = 2 + 2 * t8 + 4;
            if (ns <= 17) cc.issue(ns, bh1);
        }
    }
}

extern "C" void kernel_launch(void* const* d_in, const int* in_sizes, int n_in,
                              void* d_out, int out_size)
{
    const float* x    = (const float*)d_in[0];   // [B, L, C]
    const float* w    = (const float*)d_in[1];   // [K, C, 1]
    const float* bias = (const float*)d_in[2];   // [C]
    float*       out  = (float*)d_out;           // [B, L, C]

    dim3 grid(L_ / RCH, (C_ / 2) / TPB, B_);     // (64, 2, 8)
    dwconv_kernel<<<grid, TPB>>>(x, w, bias, out);
}

// round 3
// speedup vs baseline: 1.2458x; 1.0037x over previous
#include <cuda_runtime.h>
#include <cstdint>
#include <cstddef>

// Depthwise conv1d: B=8, L=16384, C=512, K=31, SAME, fp32.
// cp.async -> warp-private SMEM slab ring (3 deep) + f32x2 ring-accumulator.
// Sync is warp-local only: each warp's buffers are written/read by itself.
// Stream step s = 0..287, input q = l0-16+s; input q adds w[k] to slot
// (s-1-k)&31; output l0+s-31 stored from slot (s+1)&31 at end of step s.

constexpr int B_   = 8;
constexpr int L_   = 16384;
constexpr int C_   = 512;
constexpr int K_   = 31;
constexpr int RCH  = 256;          // L outputs per block
constexpr int TPB  = 128;          // 4 warps; warp owns 32 channel pairs
constexpr int CW   = C_ / 2;       // 256 u64 per L-row
constexpr int SLAB = 16;           // L-rows per smem slab
constexpr int ROWB = 2048;         // bytes per L-row (512 floats)
constexpr int NSLAB = 18;          // 288 stream rows

using u64 = unsigned long long;

__device__ __forceinline__ u64 ffma2(u64 a, u64 b, u64 c) {
    u64 d;
    asm("fma.rn.f32x2 %0, %1, %2, %3;" : "=l"(d) : "l"(a), "l"(b), "l"(c));
    return d;
}
__device__ __forceinline__ void cpa16(unsigned saddr, const void* gptr, unsigned sz) {
    asm volatile("cp.async.cg.shared.global [%0], [%1], 16, %2;\n"
                 :: "r"(saddr), "l"(gptr), "r"(sz));
}
__device__ __forceinline__ void cpcommit() { asm volatile("cp.async.commit_group;\n"); }
template <int N>
__device__ __forceinline__ void cpwait() { asm volatile("cp.async.wait_group %0;\n" :: "n"(N)); }

struct Copier {
    const char* xw;     // x base for (batch, warp's first channel pair)
    unsigned    sbase;  // shared addr of this warp's buffer[0]
    int         lane;
    int         q0;     // l0 - 16

    // Copy one slab (16 rows x 256B for this warp) into buffer buf.
    // OOB rows (SAME padding) zero-filled via src_size = 0.
    __device__ __forceinline__ void issue(int slab, int buf) const {
        if (slab >= NSLAB) { cpcommit(); return; }     // keep group count uniform
        unsigned dst = sbase + (unsigned)buf * (SLAB * 256);
        int qb = q0 + slab * SLAB;
#pragma unroll
        for (int j = 0; j < 8; ++j) {
            int idx = j * 32 + lane;        // 0..255 16B chunks
            int r = idx >> 4, o = idx & 15;
            int q = qb + r;
            int qc = q < 0 ? 0 : (q >= L_ ? L_ - 1 : q);
            unsigned sz = (q >= 0 && q < L_) ? 16u : 0u;
            cpa16(dst + (unsigned)(r * 256 + o * 16),
                  xw + (long)qc * ROWB + o * 16, sz);
        }
        cpcommit();
    }
};

// One full 16-row slab at ring phase PHASE (0 or 16). LAST: stop at u=14.
template <int PHASE, bool LAST>
__device__ __forceinline__ void do_slab(const u64* __restrict__ sl, int lane,
                                        const u64* __restrict__ wr,
                                        u64* __restrict__ acc, u64 bb,
                                        u64*& op)
{
#pragma unroll
    for (int u = 0; u < (LAST ? 15 : 16); ++u) {
        u64 v = sl[u * 32 + lane];
#pragma unroll
        for (int k = 0; k < K_; ++k) {
            const int t = (PHASE + u - 1 - k) & 31;
            acc[t] = ffma2(v, wr[k], acc[t]);
        }
        const int st = (PHASE + u + 1) & 31;
        *op = acc[st]; acc[st] = bb; op += CW;
    }
}

__global__ void __launch_bounds__(TPB, 3)
dwconv_kernel(const float* __restrict__ x, const float* __restrict__ w,
              const float* __restrict__ bias, float* __restrict__ out)
{
    __shared__ __align__(16) u64 sbuf[4][3][SLAB][32];   // 48 KB

    const int lane = threadIdx.x & 31;
    const int warp = threadIdx.x >> 5;
    const int cp   = blockIdx.y * TPB + threadIdx.x;     // channel pair
    const int cp0w = blockIdx.y * TPB + warp * 32;
    const int b    = blockIdx.z;
    const int l0   = blockIdx.x * RCH;

    Copier cc;
    cc.xw    = (const char*)x + (size_t)b * ((size_t)L_ * C_ * 4) + (size_t)cp0w * 8;
    cc.sbase = (unsigned)__cvta_generic_to_shared(&sbuf[warp][0][0][0]);
    cc.lane  = lane;
    cc.q0    = l0 - 16;

    const u64* wg = (const u64*)w;
    u64 wr[K_];
#pragma unroll
    for (int k = 0; k < K_; ++k) wr[k] = wg[k * CW + cp];
    const u64 bb = ((const u64*)bias)[cp];

    u64 acc[32];
#pragma unroll
    for (int i = 0; i < 32; ++i) acc[i] = bb;

    u64* op = (u64*)out + (size_t)b * ((size_t)L_ * CW) + (size_t)l0 * CW + cp;

    cc.issue(0, 0); cc.issue(1, 1); cc.issue(2, 2);
    const u64* sw = &sbuf[warp][0][0][0];

    // ---- slab 0 (phase 0): s = u, contributions k <= u-1, no stores ----
    cpwait<2>(); __syncwarp();
#pragma unroll
    for (int u = 1; u < 16; ++u) {
        u64 v = sw[u * 32 + lane];
#pragma unroll
        for (int k = 0; k < u; ++k) {
            const int t = u - 1 - k;
            acc[t] = ffma2(v, wr[k], acc[t]);
        }
    }
    __syncwarp(); cc.issue(3, 0);

    // ---- slab 1 (phase 16): s = 16+u, k <= 15+u; first store at s=31 ----
    cpwait<2>(); __syncwarp();
#pragma unroll
    for (int u = 0; u < 16; ++u) {
        u64 v = sw[(SLAB * 32) + u * 32 + lane];
#pragma unroll
        for (int k = 0; k <= 15 + u; ++k) {
            const int t = 15 + u - k;
            acc[t] = ffma2(v, wr[k], acc[t]);
        }
        if (u == 15) { *op = acc[0]; acc[0] = bb; op += CW; }
    }
    __syncwarp(); cc.issue(4, 1);

    // ---- slabs 2..17: full stencil; slab = 2+2i (phase 0), 3+2i (phase 16) ----
    int buf = 2;                                         // slab % 3, slab = 2
#pragma unroll 1
    for (int i = 0; i < 8; ++i) {
        // even slab (phase 0)
        cpwait<2>(); __syncwarp();
        do_slab<0, false>(sw + buf * (SLAB * 32), lane, wr, acc, bb, op);
        __syncwarp(); cc.issue(2 + 2 * i + 3, buf);
        buf = (buf == 2) ? 0 : buf + 1;

        // odd slab (phase 16)
        cpwait<2>(); __syncwarp();
        if (i < 7) do_slab<16, false>(sw + buf * (SLAB * 32), lane, wr, acc, bb, op);
        else       do_slab<16, true >(sw + buf * (SLAB * 32), lane, wr, acc, bb, op);
        __syncwarp(); cc.issue(2 + 2 * i + 4, buf);
        buf = (buf == 2) ? 0 : buf + 1;
    }
}

extern "C" void kernel_launch(void* const* d_in, const int* in_sizes, int n_in,
                              void* d_out, int out_size)
{
    const float* x    = (const float*)d_in[0];   // [B, L, C]
    const float* w    = (const float*)d_in[1];   // [K, C, 1]
    const float* bias = (const float*)d_in[2];   // [C]
    float*       out  = (float*)d_out;           // [B, L, C]

    dim3 grid(L_ / RCH, (C_ / 2) / TPB, B_);     // (64, 2, 8)
    dwconv_kernel<<<grid, TPB>>>(x, w, bias, out);
}

// round 4
// speedup vs baseline: 1.3389x; 1.0748x over previous
#include <cuda_runtime.h>
#include <cstdint>
#include <cstddef>

// Depthwise conv1d: B=8, L=16384, C=512, K=31, SAME, fp32.
// Fine-grained chunks (RCH=64) to kill wave-quantization tail; cp.async ->
// warp-private SMEM slab ring (3 deep) + f32x2 ring-accumulator stencil.
// Stream step s, input q = l0-16+s; input q adds w[k] to slot (s-1-k)&31;
// output l0+s-31 stored from slot (s+1)&31 at end of step s.

constexpr int B_   = 8;
constexpr int L_   = 16384;
constexpr int C_   = 512;
constexpr int K_   = 31;
constexpr int RCH  = 64;           // L outputs per block
constexpr int TPB  = 128;          // 4 warps; warp owns 32 channel pairs
constexpr int CW   = C_ / 2;       // 256 u64 per L-row
constexpr int SLAB = 16;           // L-rows per smem slab
constexpr int ROWB = 2048;         // bytes per L-row (512 floats)
constexpr int NSLAB = 6;           // 96 stream rows (need 95)

using u64 = unsigned long long;

__device__ __forceinline__ u64 ffma2(u64 a, u64 b, u64 c) {
    u64 d;
    asm("fma.rn.f32x2 %0, %1, %2, %3;" : "=l"(d) : "l"(a), "l"(b), "l"(c));
    return d;
}
__device__ __forceinline__ void stg_cs(u64* p, u64 v) {
    asm volatile("st.global.cs.b64 [%0], %1;" :: "l"(p), "l"(v));
}
__device__ __forceinline__ void cpa16(unsigned saddr, const void* gptr, unsigned sz) {
    asm volatile("cp.async.cg.shared.global [%0], [%1], 16, %2;\n"
                 :: "r"(saddr), "l"(gptr), "r"(sz));
}
__device__ __forceinline__ void cpcommit() { asm volatile("cp.async.commit_group;\n"); }
template <int N>
__device__ __forceinline__ void cpwait() { asm volatile("cp.async.wait_group %0;\n" :: "n"(N)); }

template <bool GUARD>
struct Copier {
    const char* xw;     // x base for (batch, warp's first channel pair)
    unsigned    sbase;  // shared addr of this warp's buffer[0] (+lane offsets)
    int         rl;     // lane>>4  (row parity this lane serves)
    int         o16;    // (lane&15)*16 (byte offset within 256B row)
    int         q0;     // l0 - 16

    // Copy one slab (16 rows x 256B for this warp) into buffer buf.
    // OOB rows (SAME padding) zero-filled via src_size = 0.
    __device__ __forceinline__ void issue(int slab, int buf) const {
        if (slab >= NSLAB) { cpcommit(); return; }   // keep group count uniform
        unsigned dst = sbase + (unsigned)buf * (SLAB * 256)
                     + (unsigned)(rl * 256 + o16);
        const int qb = q0 + slab * SLAB + rl;
        if (GUARD) {
#pragma unroll
            for (int j = 0; j < 8; ++j) {
                int q = qb + 2 * j;
                int qc = q < 0 ? 0 : (q >= L_ ? L_ - 1 : q);
                unsigned sz = (q >= 0 && q < L_) ? 16u : 0u;
                cpa16(dst + (unsigned)(j * 512), xw + (long)qc * ROWB + o16, sz);
            }
        } else {
            const char* g = xw + (long)qb * ROWB + o16;
#pragma unroll
            for (int j = 0; j < 8; ++j)
                cpa16(dst + (unsigned)(j * 512), g + (long)j * (2 * ROWB), 16u);
        }
        cpcommit();
    }
};

// One 16-row slab at ring phase PHASE (0 or 16). LAST: stop at u=14.
template <int PHASE, bool LAST>
__device__ __forceinline__ void do_slab(const u64* __restrict__ sl, int lane,
                                        const u64* __restrict__ wr,
                                        u64* __restrict__ acc, u64 bb,
                                        u64*& op)
{
#pragma unroll
    for (int u = 0; u < (LAST ? 15 : 16); ++u) {
        u64 v = sl[u * 32 + lane];
#pragma unroll
        for (int k = 0; k < K_; ++k) {
            const int t = (PHASE + u - 1 - k) & 31;
            acc[t] = ffma2(v, wr[k], acc[t]);
        }
        const int st = (PHASE + u + 1) & 31;
        stg_cs(op, acc[st]); acc[st] = bb; op += CW;
    }
}

template <bool GUARD>
__device__ __forceinline__ void conv_body(const float* __restrict__ x,
                                          const float* __restrict__ w,
                                          const float* __restrict__ bias,
                                          float* __restrict__ out,
                                          u64 (*sbuf)[3][SLAB][32])
{
    const int lane = threadIdx.x & 31;
    const int warp = threadIdx.x >> 5;
    const int cp   = blockIdx.y * TPB + threadIdx.x;     // channel pair
    const int cp0w = blockIdx.y * TPB + warp * 32;
    const int b    = blockIdx.z;
    const int l0   = blockIdx.x * RCH;

    Copier<GUARD> cc;
    cc.xw    = (const char*)x + (size_t)b * ((size_t)L_ * C_ * 4) + (size_t)cp0w * 8;
    cc.sbase = (unsigned)__cvta_generic_to_shared(&sbuf[warp][0][0][0]);
    cc.rl    = lane >> 4;
    cc.o16   = (lane & 15) * 16;
    cc.q0    = l0 - 16;

    const u64* wg = (const u64*)w;
    u64 wr[K_];
#pragma unroll
    for (int k = 0; k < K_; ++k) wr[k] = wg[k * CW + cp];
    const u64 bb = ((const u64*)bias)[cp];

    u64 acc[32];
#pragma unroll
    for (int i = 0; i < 32; ++i) acc[i] = bb;

    u64* op = (u64*)out + (size_t)b * ((size_t)L_ * CW) + (size_t)l0 * CW + cp;

    cc.issue(0, 0); cc.issue(1, 1); cc.issue(2, 2);
    const u64* sw = &sbuf[warp][0][0][0];

    // ---- slab 0 (phase 0): s = u, contributions k <= u-1, no stores ----
    cpwait<2>(); __syncwarp();
#pragma unroll
    for (int u = 1; u < 16; ++u) {
        u64 v = sw[u * 32 + lane];
#pragma unroll
        for (int k = 0; k < u; ++k) {
            const int t = u - 1 - k;
            acc[t] = ffma2(v, wr[k], acc[t]);
        }
    }
    __syncwarp(); cc.issue(3, 0);

    // ---- slab 1 (phase 16): s = 16+u, k <= 15+u; first store at s=31 ----
    cpwait<2>(); __syncwarp();
#pragma unroll
    for (int u = 0; u < 16; ++u) {
        u64 v = sw[(SLAB * 32) + u * 32 + lane];
#pragma unroll
        for (int k = 0; k <= 15 + u; ++k) {
            const int t = 15 + u - k;
            acc[t] = ffma2(v, wr[k], acc[t]);
        }
        if (u == 15) { stg_cs(op, acc[0]); acc[0] = bb; op += CW; }
    }
    __syncwarp(); cc.issue(4, 1);

    // ---- slabs 2..5 (full stencil; phases alternate; slab5 is LAST) ----
    cpwait<2>(); __syncwarp();
    do_slab<0, false>(sw + 2 * (SLAB * 32), lane, wr, acc, bb, op);
    __syncwarp(); cc.issue(5, 2);

    cpwait<2>(); __syncwarp();
    do_slab<16, false>(sw + 0 * (SLAB * 32), lane, wr, acc, bb, op);
    __syncwarp(); cc.issue(6, 0);     // dummy

    cpwait<2>(); __syncwarp();
    do_slab<0, false>(sw + 1 * (SLAB * 32), lane, wr, acc, bb, op);
    __syncwarp(); cc.issue(7, 1);     // dummy

    cpwait<2>(); __syncwarp();
    do_slab<16, true>(sw + 2 * (SLAB * 32), lane, wr, acc, bb, op);
}

__global__ void __launch_bounds__(TPB, 3)
dwconv_kernel(const float* __restrict__ x, const float* __restrict__ w,
              const float* __restrict__ bias, float* __restrict__ out)
{
    __shared__ __align__(16) u64 sbuf[4][3][SLAB][32];   // 48 KB

    if (blockIdx.x == 0 || blockIdx.x == (L_ / RCH) - 1)
        conv_body<true>(x, w, bias, out, sbuf);
    else
        conv_body<false>(x, w, bias, out, sbuf);
}

extern "C" void kernel_launch(void* const* d_in, const int* in_sizes, int n_in,
                              void* d_out, int out_size)
{
    const float* x    = (const float*)d_in[0];   // [B, L, C]
    const float* w    = (const float*)d_in[1];   // [K, C, 1]
    const float* bias = (const float*)d_in[2];   // [C]
    float*       out  = (float*)d_out;           // [B, L, C]

    dim3 grid(L_ / RCH, (C_ / 2) / TPB, B_);     // (256, 2, 8) = 4096 CTAs
    dwconv_kernel<<<grid, TPB>>>(x, w, bias, out);
}

// round 5
// speedup vs baseline: 1.3578x; 1.0141x over previous
#include <cuda_runtime.h>
#include <cstdint>
#include <cstddef>

// Depthwise conv1d: B=8, L=16384, C=512, K=31, SAME, fp32.
// RCH=64 chunks (tail-free), cp.async -> warp-private SMEM slab ring (3 deep),
// f32x2 ring-accumulator stencil with v-prefetch + descending-k FMA order.
// Stream step s, input q = l0-16+s; input q adds w[k] to slot (s-1-k)&31;
// output l0+s-31 stored from slot (s+1)&31 (produced by the k=30 FMA).

constexpr int B_   = 8;
constexpr int L_   = 16384;
constexpr int C_   = 512;
constexpr int K_   = 31;
constexpr int RCH  = 64;           // L outputs per block
constexpr int TPB  = 128;          // 4 warps; warp owns 32 channel pairs
constexpr int CW   = C_ / 2;       // 256 u64 per L-row
constexpr int SLAB = 16;           // L-rows per smem slab
constexpr int ROWB = 2048;         // bytes per L-row (512 floats)
constexpr int NSLAB = 6;           // 96 stream rows (need 95)

using u64 = unsigned long long;

__device__ __forceinline__ u64 ffma2(u64 a, u64 b, u64 c) {
    u64 d;
    asm("fma.rn.f32x2 %0, %1, %2, %3;" : "=l"(d) : "l"(a), "l"(b), "l"(c));
    return d;
}
__device__ __forceinline__ void stg_cs(u64* p, u64 v) {
    asm volatile("st.global.cs.b64 [%0], %1;" :: "l"(p), "l"(v));
}
__device__ __forceinline__ void cpa16(unsigned saddr, const void* gptr, unsigned sz) {
    asm volatile("cp.async.cg.shared.global [%0], [%1], 16, %2;\n"
                 :: "r"(saddr), "l"(gptr), "r"(sz));
}
__device__ __forceinline__ void cpcommit() { asm volatile("cp.async.commit_group;\n"); }
template <int N>
__device__ __forceinline__ void cpwait() { asm volatile("cp.async.wait_group %0;\n" :: "n"(N)); }

template <bool GUARD>
struct Copier {
    const char* xw;     // x base for (batch, warp's first channel pair)
    unsigned    sbase;  // shared addr of this warp's buffer[0] (+lane offsets)
    int         rl;     // lane>>4  (row parity this lane serves)
    int         o16;    // (lane&15)*16 (byte offset within 256B row)
    int         q0;     // l0 - 16

    __device__ __forceinline__ void issue(int slab, int buf) const {
        if (slab >= NSLAB) { cpcommit(); return; }   // uniform group count
        unsigned dst = sbase + (unsigned)buf * (SLAB * 256)
                     + (unsigned)(rl * 256 + o16);
        const int qb = q0 + slab * SLAB + rl;
        if (GUARD) {
#pragma unroll
            for (int j = 0; j < 8; ++j) {
                int q = qb + 2 * j;
                int qc = q < 0 ? 0 : (q >= L_ ? L_ - 1 : q);
                unsigned sz = (q >= 0 && q < L_) ? 16u : 0u;
                cpa16(dst + (unsigned)(j * 512), xw + (long)qc * ROWB + o16, sz);
            }
        } else {
            const char* g = xw + (long)qb * ROWB + o16;
#pragma unroll
            for (int j = 0; j < 8; ++j)
                cpa16(dst + (unsigned)(j * 512), g + (long)j * (2 * ROWB), 16u);
        }
        cpcommit();
    }
};

// One 16-row slab at ring phase PHASE (0 or 16). LAST: stop at u=14.
// v-prefetch: load v[u+1] before the FMA chain of step u.
// Descending k: k=30 FMA (producer of the stored slot) issues first.
template <int PHASE, bool LAST>
__device__ __forceinline__ void do_slab(const u64* __restrict__ sl, int lane,
                                        const u64* __restrict__ wr,
                                        u64* __restrict__ acc, u64 bb,
                                        u64*& op)
{
    constexpr int N = LAST ? 15 : 16;
    u64 v = sl[lane];
#pragma unroll
    for (int u = 0; u < N; ++u) {
        u64 vn = (u + 1 < 16) ? sl[(u + 1) * 32 + lane] : v;
#pragma unroll
        for (int k = K_ - 1; k >= 0; --k) {
            const int t = (PHASE + u - 1 - k) & 31;
            acc[t] = ffma2(v, wr[k], acc[t]);
        }
        const int st = (PHASE + u + 1) & 31;       // written by k=30 (first)
        stg_cs(op, acc[st]); acc[st] = bb; op += CW;
        v = vn;
    }
}

template <bool GUARD>
__device__ __forceinline__ void conv_body(const float* __restrict__ x,
                                          const float* __restrict__ w,
                                          const float* __restrict__ bias,
                                          float* __restrict__ out,
                                          u64 (*sbuf)[3][SLAB][32])
{
    const int lane = threadIdx.x & 31;
    const int warp = threadIdx.x >> 5;
    const int cp   = blockIdx.y * TPB + threadIdx.x;     // channel pair
    const int cp0w = blockIdx.y * TPB + warp * 32;
    const int b    = blockIdx.z;
    const int l0   = blockIdx.x * RCH;

    Copier<GUARD> cc;
    cc.xw    = (const char*)x + (size_t)b * ((size_t)L_ * C_ * 4) + (size_t)cp0w * 8;
    cc.sbase = (unsigned)__cvta_generic_to_shared(&sbuf[warp][0][0][0]);
    cc.rl    = lane >> 4;
    cc.o16   = (lane & 15) * 16;
    cc.q0    = l0 - 16;

    const u64* wg = (const u64*)w;
    u64 wr[K_];
#pragma unroll
    for (int k = 0; k < K_; ++k) wr[k] = wg[k * CW + cp];
    const u64 bb = ((const u64*)bias)[cp];

    u64 acc[32];
#pragma unroll
    for (int i = 0; i < 32; ++i) acc[i] = bb;

    u64* op = (u64*)out + (size_t)b * ((size_t)L_ * CW) + (size_t)l0 * CW + cp;

    cc.issue(0, 0); cc.issue(1, 1); cc.issue(2, 2);
    const u64* sw = &sbuf[warp][0][0][0];

    // ---- slab 0 (phase 0): s = u, contributions k <= u-1, no stores ----
    cpwait<2>(); __syncwarp();
    {
        u64 v = sw[32 + lane];                       // u=1 first
#pragma unroll
        for (int u = 1; u < 16; ++u) {
            u64 vn = (u + 1 < 16) ? sw[(u + 1) * 32 + lane] : v;
#pragma unroll
            for (int k = u - 1; k >= 0; --k) {
                const int t = u - 1 - k;
                acc[t] = ffma2(v, wr[k], acc[t]);
            }
            v = vn;
        }
    }
    __syncwarp(); cc.issue(3, 0);

    // ---- slab 1 (phase 16): s = 16+u, k <= 15+u; first store at s=31 ----
    cpwait<2>(); __syncwarp();
    {
        const u64* sl = sw + SLAB * 32;
        u64 v = sl[lane];
#pragma unroll
        for (int u = 0; u < 16; ++u) {
            u64 vn = (u + 1 < 16) ? sl[(u + 1) * 32 + lane] : v;
#pragma unroll
            for (int k = 15 + u; k >= 0; --k) {
                const int t = 15 + u - k;
                acc[t] = ffma2(v, wr[k], acc[t]);
            }
            if (u == 15) { stg_cs(op, acc[0]); acc[0] = bb; op += CW; }
            v = vn;
        }
    }
    __syncwarp(); cc.issue(4, 1);

    // ---- slabs 2..5 (full stencil; alternating phase; slab5 is LAST) ----
    cpwait<2>(); __syncwarp();
    do_slab<0, false>(sw + 2 * (SLAB * 32), lane, wr, acc, bb, op);
    __syncwarp(); cc.issue(5, 2);

    cpwait<2>(); __syncwarp();
    do_slab<16, false>(sw + 0 * (SLAB * 32), lane, wr, acc, bb, op);
    __syncwarp(); cc.issue(6, 0);     // dummy

    cpwait<2>(); __syncwarp();
    do_slab<0, false>(sw + 1 * (SLAB * 32), lane, wr, acc, bb, op);
    __syncwarp(); cc.issue(7, 1);     // dummy

    cpwait<2>(); __syncwarp();
    do_slab<16, true>(sw + 2 * (SLAB * 32), lane, wr, acc, bb, op);
}

__global__ void __launch_bounds__(TPB, 3)
dwconv_kernel(const float* __restrict__ x, const float* __restrict__ w,
              const float* __restrict__ bias, float* __restrict__ out)
{
    __shared__ __align__(16) u64 sbuf[4][3][SLAB][32];   // 48 KB

    if (blockIdx.x == 0 || blockIdx.x == (L_ / RCH) - 1)
        conv_body<true>(x, w, bias, out, sbuf);
    else
        conv_body<false>(x, w, bias, out, sbuf);
}

extern "C" void kernel_launch(void* const* d_in, const int* in_sizes, int n_in,
                              void* d_out, int out_size)
{
    const float* x    = (const float*)d_in[0];   // [B, L, C]
    const float* w    = (const float*)d_in[1];   // [K, C, 1]
    const float* bias = (const float*)d_in[2];   // [C]
    float*       out  = (float*)d_out;           // [B, L, C]

    dim3 grid(L_ / RCH, (C_ / 2) / TPB, B_);     // (256, 2, 8) = 4096 CTAs
    dwconv_kernel<<<grid, TPB>>>(x, w, bias, out);
}